// round 12
// baseline (speedup 1.0000x reference)
#include <cuda_runtime.h>
#include <cstdint>

static constexpr int B  = 2;
static constexpr int C  = 64;
static constexpr int H1 = 256, W1 = 256;
static constexpr int H2 = 128, W2 = 128;

// ---------------------------------------------------------------------------
// Packed f32x2 helpers
// ---------------------------------------------------------------------------
__device__ __forceinline__ unsigned long long pack2(float x)
{
    unsigned long long r;
    asm("mov.b64 %0, {%1, %1};" : "=l"(r) : "f"(x));
    return r;
}
__device__ __forceinline__ unsigned long long pack_pair(float lo, float hi)
{
    unsigned long long r;
    asm("mov.b64 %0, {%1, %2};" : "=l"(r) : "f"(lo), "f"(hi));
    return r;
}
__device__ __forceinline__ void fma2(unsigned long long& acc,
                                     unsigned long long a, unsigned long long b)
{
    asm("fma.rn.f32x2 %0, %1, %2, %0;" : "+l"(acc) : "l"(a), "l"(b));
}
__device__ __forceinline__ float2 unpack2(unsigned long long v)
{
    float2 r;
    asm("mov.b64 {%0, %1}, %2;" : "=f"(r.x), "=f"(r.y) : "l"(v));
    return r;
}

// ---------------------------------------------------------------------------
// cp.async helpers (4-byte, zero-fill on invalid via src-size = 0)
// ---------------------------------------------------------------------------
__device__ __forceinline__ void cp_async4(uint32_t dst_smem, const float* src, bool valid)
{
    int sz = valid ? 4 : 0;
    asm volatile("cp.async.ca.shared.global [%0], [%1], 4, %2;"
                 :: "r"(dst_smem), "l"(src), "r"(sz));
}
__device__ __forceinline__ void cp_commit() { asm volatile("cp.async.commit_group;"); }
__device__ __forceinline__ void cp_wait0()  { asm volatile("cp.async.wait_group 0;"); }
__device__ __forceinline__ uint32_t smem_u32(const void* p)
{
    return (uint32_t)__cvta_generic_to_shared(p);
}

// ---------------------------------------------------------------------------
// Device scratch
// ---------------------------------------------------------------------------
__device__ float g_fea2down[B * 128 * H2 * W2];
__device__ float g_fea1    [B * C   * H1 * W1];
__device__ float g_fea2    [B * C   * H2 * W2];
__device__ float g_up1     [B * C   * H1 * W1];
__device__ float g_fea     [B * C   * H1 * W1];
__device__ float g_off1    [B * 18  * H1 * W1];
__device__ float g_fea11   [B * C   * H1 * W1];
__device__ float g_rs2     [B * C   * H2 * W2];
__device__ float g_off2    [B * 18  * H2 * W2];
__device__ float g_fea2d   [B * C   * H2 * W2];
__device__ float g_up2     [B * C   * H1 * W1];
__device__ float g_wq1     [4 * C * 4 * C];
__device__ float g_wq2     [4 * C * 4 * C];

// ---------------------------------------------------------------------------
// conv3x3 v6: block = 32 cols x 8 rows x 32 out-ch. 128 threads:
//   colg = tid&3 (8-col group), row = (tid>>2)&7, cog = tid>>5 (8-ch group).
// Each thread: 8 adjacent pixels x 8 channels, accumulated as 4 pixel-PAIRS
// (f32x2) per channel -> 32 ull = 64 regs. Weight reads are warp-broadcast
// (all lanes of a warp share cog). cp.async double-buffered staging.
// Requires Cout % 32 == 0, Ho % 8 == 0, Wo % 32 == 0, Cin % CI_BLK == 0.
// ---------------------------------------------------------------------------
template <int STRIDE, int CI_BLK>
__global__ __launch_bounds__(128, 4)
void conv3x3_v6(const float* __restrict__ inA, const float* __restrict__ inB,
                int C0, int Cin,
                const float* __restrict__ w, const float* __restrict__ bias,
                float* __restrict__ out, int Cout,
                int H, int W, int Ho, int Wo)
{
    constexpr int XR = 7 * STRIDE + 3;                  // 10 / 17 input rows
    constexpr int XC = 31 * STRIDE + 3;                 // 34 / 65 input cols
    constexpr int XP = XC + 1;                          // 35 / 66 pitch
    constexpr int NX = 7 * STRIDE + 3;                  // scalars per kh (10/17)
    __shared__ __align__(16) float xs[2][CI_BLK][XR * XP];
    __shared__ __align__(16) float w_s[2][CI_BLK][9][32];

    const int tid  = threadIdx.x;
    const int colg = tid & 3;
    const int row  = (tid >> 2) & 7;
    const int cog  = tid >> 5;
    const int col0 = colg * 8;
    const int nchunk = Cout >> 5;
    const int b     = blockIdx.z / nchunk;
    const int chunk = blockIdx.z % nchunk;
    const int co_base = chunk * 32;
    const int ow0 = blockIdx.x * 32;
    const int oh0 = blockIdx.y * 8;
    const int HW = H * W;

    unsigned long long acc[8][4];
#pragma unroll
    for (int co = 0; co < 8; co++)
#pragma unroll
        for (int j = 0; j < 4; j++) acc[co][j] = 0ull;

    auto stage = [&](int sb, int cb) {
        for (int i = tid; i < CI_BLK * XR * XC; i += 128) {
            int ci  = i / (XR * XC);
            int rem = i % (XR * XC);
            int lr = rem / XC, lc = rem % XC;
            int r = oh0 * STRIDE - 1 + lr;
            int c = ow0 * STRIDE - 1 + lc;
            int cig = cb + ci;
            const float* src = (cig < C0)
                ? (inA + ((size_t)b * C0 + cig) * HW)
                : (inB + ((size_t)b * (Cin - C0) + (cig - C0)) * HW);
            bool valid = (r >= 0 && r < H && c >= 0 && c < W);
            cp_async4(smem_u32(&xs[sb][ci][lr * XP + lc]),
                      src + (valid ? r * W + c : 0), valid);
        }
        for (int i = tid; i < CI_BLK * 9 * 32; i += 128) {
            int o = i & 31, tap = (i >> 5) % 9, ci = i / 288;
            cp_async4(smem_u32(&w_s[sb][ci][tap][o]),
                      w + ((size_t)(co_base + o) * Cin + cb + ci) * 9 + tap, true);
        }
        cp_commit();
    };

    stage(0, 0);
    const int nst = Cin / CI_BLK;
    for (int s = 0; s < nst; s++) {
        cp_wait0();
        __syncthreads();
        if (s + 1 < nst) stage((s + 1) & 1, (s + 1) * CI_BLK);
        const int sb = s & 1;

        for (int ci = 0; ci < CI_BLK; ci++) {
            const float* xc = xs[sb][ci];
#pragma unroll
            for (int kh = 0; kh < 3; kh++) {
                // load the activation window for this row of taps
                float x[NX];
                {
                    const float* xr = xc + (row * STRIDE + kh) * XP + col0 * STRIDE;
#pragma unroll
                    for (int i = 0; i < NX; i++) x[i] = xr[i];
                }
#pragma unroll
                for (int kw = 0; kw < 3; kw++) {
                    unsigned long long ap[4];
#pragma unroll
                    for (int j = 0; j < 4; j++)
                        ap[j] = pack_pair(x[(2 * j) * STRIDE + kw],
                                          x[(2 * j + 1) * STRIDE + kw]);
                    const float* wp = w_s[sb][ci][kh * 3 + kw] + cog * 8;
#pragma unroll
                    for (int co = 0; co < 8; co++) {
                        unsigned long long ww = pack2(wp[co]);
                        fma2(acc[co][0], ap[0], ww);
                        fma2(acc[co][1], ap[1], ww);
                        fma2(acc[co][2], ap[2], ww);
                        fma2(acc[co][3], ap[3], ww);
                    }
                }
            }
        }
    }

    const int oh = oh0 + row;
#pragma unroll
    for (int co = 0; co < 8; co++) {
        int og = co_base + cog * 8 + co;
        float bv = bias[og];
        float* op = out + (((size_t)b * Cout + og) * Ho + oh) * Wo + ow0 + col0;
#pragma unroll
        for (int j = 0; j < 4; j++) {
            float2 v = unpack2(acc[co][j]);
            op[2 * j]     = v.x + bv;
            op[2 * j + 1] = v.y + bv;
        }
    }
}

// ---------------------------------------------------------------------------
// Old-style 3x3 conv for the offset heads (Cout=18, CO=20 register block).
// ---------------------------------------------------------------------------
template <int STRIDE, int CO>
__global__ __launch_bounds__(256)
void conv3x3_kernel(const float* __restrict__ inA, const float* __restrict__ inB,
                    int C0, int Cin,
                    const float* __restrict__ w, const float* __restrict__ bias,
                    float* __restrict__ out, int Cout,
                    int H, int W, int Ho, int Wo)
{
    constexpr int XR = 7 * STRIDE + 3;
    constexpr int XC = 31 * STRIDE + 3;
    constexpr int XP = XC + (STRIDE == 2 ? 1 : 0);
    __shared__ __align__(16) float xs[XR * XP];
    __shared__ __align__(16) float w_s[9 * CO];

    const int tid = threadIdx.x;
    const int tx = tid & 31, ty = tid >> 5;
    const int nchunk = (Cout + CO - 1) / CO;
    const int b     = blockIdx.z / nchunk;
    const int chunk = blockIdx.z % nchunk;
    const int co_base = chunk * CO;
    const int ow0 = blockIdx.x * 32;
    const int oh0 = blockIdx.y * 8;
    const int HW = H * W;

    unsigned long long acc[CO / 2];
#pragma unroll
    for (int o = 0; o < CO / 2; o++) acc[o] = 0ull;

    for (int ci = 0; ci < Cin; ci++) {
        const float* src = (ci < C0)
            ? (inA + ((size_t)b * C0 + ci) * HW)
            : (inB + ((size_t)b * (Cin - C0) + (ci - C0)) * HW);
        __syncthreads();
        for (int i = tid; i < XR * XC; i += 256) {
            int lr = i / XC, lc = i % XC;
            int r = oh0 * STRIDE - 1 + lr;
            int c = ow0 * STRIDE - 1 + lc;
            xs[lr * XP + lc] = (r >= 0 && r < H && c >= 0 && c < W) ? src[r * W + c] : 0.f;
        }
        for (int i = tid; i < 9 * CO; i += 256) {
            int tap = i / CO, o = i % CO;
            int og = co_base + o;
            w_s[tap * CO + o] = (og < Cout) ? w[((size_t)og * Cin + ci) * 9 + tap] : 0.f;
        }
        __syncthreads();

        float xv[9];
#pragma unroll
        for (int kh = 0; kh < 3; kh++)
#pragma unroll
            for (int kw = 0; kw < 3; kw++)
                xv[kh * 3 + kw] = xs[(ty * STRIDE + kh) * XP + tx * STRIDE + kw];

#pragma unroll
        for (int tap = 0; tap < 9; tap++) {
            unsigned long long xx = pack2(xv[tap]);
            const ulonglong2* w2 = (const ulonglong2*)(w_s + tap * CO);
#pragma unroll
            for (int o4 = 0; o4 < CO / 4; o4++) {
                ulonglong2 wv = w2[o4];
                fma2(acc[o4 * 2 + 0], xx, wv.x);
                fma2(acc[o4 * 2 + 1], xx, wv.y);
            }
        }
    }

    const int oh = oh0 + ty, ow = ow0 + tx;
    if (oh < Ho && ow < Wo) {
#pragma unroll
        for (int o2 = 0; o2 < CO / 2; o2++) {
            float2 v = unpack2(acc[o2]);
            int og0 = co_base + 2 * o2;
            if (og0 < Cout)
                out[(((size_t)b * Cout + og0) * Ho + oh) * Wo + ow] = v.x + bias[og0];
            if (og0 + 1 < Cout)
                out[(((size_t)b * Cout + og0 + 1) * Ho + oh) * Wo + ow] = v.y + bias[og0 + 1];
        }
    }
}

// ---------------------------------------------------------------------------
// Weight repack for transposed conv (4x4, stride 2, pad 1).
// ---------------------------------------------------------------------------
__global__ void prep_wq_kernel(const float* __restrict__ w, float* __restrict__ wq)
{
    int idx = blockIdx.x * 256 + threadIdx.x;
    if (idx >= 4 * C * 4 * C) return;
    int o  = idx & 63;
    int t  = (idx >> 6) & 3;
    int ci = (idx >> 8) & 63;
    int pc = idx >> 14;
    int pa = pc >> 1, pb = pc & 1;
    int di = t >> 1, dj = t & 1;
    int kh = 3 - pa - 2 * di;
    int kw = 3 - pb - 2 * dj;
    wq[idx] = w[((ci * C + o) * 4 + kh) * 4 + kw];
}

// ---------------------------------------------------------------------------
// convt v2 (kept): 128 threads, 2 px/thread, 32 out-ch per z-slice,
// 8-channel ci chunks. blockIdx.z = ((b*4 + pc)*2 + coh)
// ---------------------------------------------------------------------------
template <int CI_BLK>
__global__ __launch_bounds__(128)
void convt_v2(const float* __restrict__ in, const float* __restrict__ wq,
              const float* __restrict__ bias, float* __restrict__ out,
              int Hin, int Win)
{
    __shared__ __align__(16) float xs[CI_BLK][9 * 35];
    __shared__ __align__(16) float w_s[CI_BLK][4][32];

    const int tid = threadIdx.x;
    const int tx = tid & 15, ty = tid >> 4;
    const int zc = blockIdx.z;
    const int b   = zc >> 3;
    const int pc  = (zc >> 1) & 3;
    const int coh = zc & 1;
    const int co_base = coh * 32;
    const int pa = pc >> 1, pb = pc & 1;
    const int j0 = blockIdx.x * 32;
    const int i0 = blockIdx.y * 8;
    const int HWin = Hin * Win;
    const float* inb = in + (size_t)b * C * HWin;

    unsigned long long acc[2][16];
#pragma unroll
    for (int bb = 0; bb < 2; bb++)
#pragma unroll
        for (int o = 0; o < 16; o++) acc[bb][o] = 0ull;

    for (int cb = 0; cb < C; cb += CI_BLK) {
        __syncthreads();
        for (int i = tid; i < CI_BLK * 9 * 34; i += 128) {
            int ci = i / (9 * 34);
            int rem = i % (9 * 34);
            int lr = rem / 34, lc = rem % 34;
            int r = i0 + pa - 1 + lr;
            int c = j0 + pb - 1 + lc;
            xs[ci][lr * 35 + lc] =
                (r >= 0 && r < Hin && c >= 0 && c < Win) ? inb[(size_t)(cb + ci) * HWin + r * Win + c] : 0.f;
        }
        for (int i = tid; i < CI_BLK * 4 * 32; i += 128) {
            int o = i & 31, t = (i >> 5) & 3, ci = i >> 7;
            w_s[ci][t][o] = wq[(size_t)pc * (C * 4 * C) + (cb + ci) * (4 * C) + t * C + co_base + o];
        }
        __syncthreads();

        for (int ci = 0; ci < CI_BLK; ci++) {
            const float* xc = xs[ci];
            float xv[2][2][2];
#pragma unroll
            for (int di = 0; di < 2; di++)
#pragma unroll
                for (int bb = 0; bb < 2; bb++)
#pragma unroll
                    for (int dj = 0; dj < 2; dj++)
                        xv[di][bb][dj] = xc[(ty + di) * 35 + tx + 16 * bb + dj];

#pragma unroll
            for (int t = 0; t < 4; t++) {
                int di = t >> 1, dj = t & 1;
                unsigned long long xx[2];
                xx[0] = pack2(xv[di][0][dj]);
                xx[1] = pack2(xv[di][1][dj]);
                const ulonglong2* w2 = (const ulonglong2*)w_s[ci][t];
#pragma unroll
                for (int o8 = 0; o8 < 8; o8++) {
                    ulonglong2 wv = w2[o8];
#pragma unroll
                    for (int bb = 0; bb < 2; bb++) {
                        fma2(acc[bb][o8 * 2 + 0], xx[bb], wv.x);
                        fma2(acc[bb][o8 * 2 + 1], xx[bb], wv.y);
                    }
                }
            }
        }
    }

    const int Hout = 2 * Hin, Wout = 2 * Win;
    const int oh = 2 * (i0 + ty) + pa;
#pragma unroll
    for (int bb = 0; bb < 2; bb++) {
        int ow = 2 * (j0 + tx + 16 * bb) + pb;
#pragma unroll
        for (int o2 = 0; o2 < 16; o2++) {
            float2 v = unpack2(acc[bb][o2]);
            int og = co_base + 2 * o2;
            out[(((size_t)b * C + og) * Hout + oh) * Wout + ow]     = v.x + bias[og];
            out[(((size_t)b * C + og + 1) * Hout + oh) * Wout + ow] = v.y + bias[og + 1];
        }
    }
}

// ---------------------------------------------------------------------------
// 1x1 conv over (a + b2), C->C (256 threads, 1 px, 64 acc regs).
// ---------------------------------------------------------------------------
__global__ __launch_bounds__(256)
void conv1x1_add_kernel(const float* __restrict__ a, const float* __restrict__ b2,
                        const float* __restrict__ w, const float* __restrict__ bias,
                        float* __restrict__ out, int HW)
{
    __shared__ __align__(16) float w_s[C * C];   // [ci][o]
    const int tid = threadIdx.x;
    for (int i = tid; i < C * C; i += 256) {
        int ci = i >> 6, o = i & 63;
        w_s[i] = w[o * C + ci];
    }
    __syncthreads();

    const int pix = blockIdx.x * 256 + tid;
    const int b = blockIdx.y;
    if (pix >= HW) return;
    const float* ab = a  + (size_t)b * C * HW + pix;
    const float* bb = b2 + (size_t)b * C * HW + pix;

    unsigned long long acc[C / 2];
#pragma unroll
    for (int o = 0; o < C / 2; o++) acc[o] = 0ull;

    for (int ci = 0; ci < C; ci++) {
        unsigned long long xx = pack2(ab[(size_t)ci * HW] + bb[(size_t)ci * HW]);
        const ulonglong2* w2 = (const ulonglong2*)(w_s + ci * C);
#pragma unroll
        for (int o4 = 0; o4 < C / 4; o4++) {
            ulonglong2 wv = w2[o4];
            fma2(acc[o4 * 2 + 0], xx, wv.x);
            fma2(acc[o4 * 2 + 1], xx, wv.y);
        }
    }
    float* ob = out + (size_t)b * C * HW + pix;
#pragma unroll
    for (int o2 = 0; o2 < C / 2; o2++) {
        float2 v = unpack2(acc[o2]);
        ob[(size_t)(2 * o2) * HW]     = v.x + bias[2 * o2];
        ob[(size_t)(2 * o2 + 1) * HW] = v.y + bias[2 * o2 + 1];
    }
}

// ---------------------------------------------------------------------------
// Deformable conv (256 threads, 1 px, 64 acc regs) with cp.async
// double-buffered per-tap weight staging. Reference-exact.
// ---------------------------------------------------------------------------
__global__ __launch_bounds__(256)
void deform_db(const float* __restrict__ x, const float* __restrict__ off,
               const float* __restrict__ w, const float* __restrict__ bias,
               float* __restrict__ out, int H, int W)
{
    __shared__ __align__(16) float w_s[2][C * C];   // [c][o], double-buffered
    const int tid = threadIdx.x;
    const int tx = tid & 31, ty = tid >> 5;
    const int ow = blockIdx.x * 32 + tx;
    const int oh = blockIdx.y * 8 + ty;
    const int b  = blockIdx.z;
    const int HW = H * W;
    const float* xb   = x   + (size_t)b * C * HW;
    const float* offb = off + (size_t)b * 18 * HW;
    const int pix = oh * W + ow;

    unsigned long long acc[C / 2];
#pragma unroll
    for (int o = 0; o < C / 2; o++) acc[o] = 0ull;

    const float rmax = (float)(H + 1);
    const float cmax = (float)(W + 1);

    auto stage = [&](int sb, int n) {
        for (int i = tid; i < C * C; i += 256) {
            int c = i >> 6, o = i & 63;
            cp_async4(smem_u32(&w_s[sb][i]), w + (size_t)o * (C * 9) + c * 9 + n, true);
        }
        cp_commit();
    };

    stage(0, 0);
    for (int n = 0; n < 9; n++) {
        cp_wait0();
        __syncthreads();
        if (n + 1 < 9) stage((n + 1) & 1, n + 1);
        const float* ws = w_s[n & 1];

        float offr = offb[(size_t)n * HW + pix];
        float offc = offb[(size_t)(9 + n) * HW + pix];
        float pr  = (float)(oh + (n / 3)) + offr;
        float pcc = (float)(ow + (n % 3)) + offc;
        pr  = fminf(fmaxf(pr, 0.f), rmax);
        pcc = fminf(fmaxf(pcc, 0.f), cmax);
        float r0f = floorf(pr), c0f = floorf(pcc);
        int r0 = (int)r0f, c0 = (int)c0f;
        int r1 = min(r0 + 1, H + 1), c1 = min(c0 + 1, W + 1);
        float fr = pr - r0f, fc = pcc - c0f;
        float w00 = (1.f - fr) * (1.f - fc);
        float w01 = (1.f - fr) * fc;
        float w10 = fr * (1.f - fc);
        float w11 = fr * fc;

        int rr0 = r0 - 1, rr1 = r1 - 1, cc0 = c0 - 1, cc1 = c1 - 1;
        bool vr0 = (rr0 >= 0) && (rr0 < H);
        bool vr1 = (rr1 >= 0) && (rr1 < H);
        bool vc0 = (cc0 >= 0) && (cc0 < W);
        bool vc1 = (cc1 >= 0) && (cc1 < W);
        float m00 = (vr0 && vc0) ? w00 : 0.f;
        float m01 = (vr0 && vc1) ? w01 : 0.f;
        float m10 = (vr1 && vc0) ? w10 : 0.f;
        float m11 = (vr1 && vc1) ? w11 : 0.f;
        int sr0 = vr0 ? rr0 : 0, sr1 = vr1 ? rr1 : 0;
        int sc0 = vc0 ? cc0 : 0, sc1 = vc1 ? cc1 : 0;
        int i00 = sr0 * W + sc0;
        int i01 = sr0 * W + sc1;
        int i10 = sr1 * W + sc0;
        int i11 = sr1 * W + sc1;

        for (int c = 0; c < C; c++) {
            const float* xc = xb + (size_t)c * HW;
            float v = m00 * xc[i00] + m01 * xc[i01] + m10 * xc[i10] + m11 * xc[i11];
            unsigned long long vv = pack2(v);
            const ulonglong2* w2 = (const ulonglong2*)(ws + c * C);
#pragma unroll
            for (int o4 = 0; o4 < C / 4; o4++) {
                ulonglong2 wv = w2[o4];
                fma2(acc[o4 * 2 + 0], vv, wv.x);
                fma2(acc[o4 * 2 + 1], vv, wv.y);
            }
        }
    }

    if (oh < H && ow < W) {
#pragma unroll
        for (int o2 = 0; o2 < C / 2; o2++) {
            float2 v = unpack2(acc[o2]);
            out[(((size_t)b * C + 2 * o2) * H + oh) * W + ow]     = v.x + bias[2 * o2];
            out[(((size_t)b * C + 2 * o2 + 1) * H + oh) * W + ow] = v.y + bias[2 * o2 + 1];
        }
    }
}

// ---------------------------------------------------------------------------
// Launch
// ---------------------------------------------------------------------------
static float* sym(const void* s)
{
    void* p = nullptr;
    cudaGetSymbolAddress(&p, s);
    return (float*)p;
}

extern "C" void kernel_launch(void* const* d_in, const int* in_sizes, int n_in,
                              void* d_out, int out_size)
{
    const float* dem      = (const float*)d_in[0];
    const float* rs       = (const float*)d_in[1];
    const float* w_down1  = (const float*)d_in[2];
    const float* b_down1  = (const float*)d_in[3];
    const float* w_c1     = (const float*)d_in[4];
    const float* b_c1     = (const float*)d_in[5];
    const float* w_c12    = (const float*)d_in[6];
    const float* b_c12    = (const float*)d_in[7];
    const float* w_up1    = (const float*)d_in[8];
    const float* b_up1    = (const float*)d_in[9];
    const float* w_downrs = (const float*)d_in[10];
    const float* b_downrs = (const float*)d_in[11];
    const float* w_off    = (const float*)d_in[12];
    const float* b_off    = (const float*)d_in[13];
    const float* w_c3     = (const float*)d_in[14];
    const float* b_c3     = (const float*)d_in[15];
    const float* w_d1o    = (const float*)d_in[16];
    const float* b_d1o    = (const float*)d_in[17];
    const float* w_d1     = (const float*)d_in[18];
    const float* b_d1     = (const float*)d_in[19];
    const float* w_d2o    = (const float*)d_in[20];
    const float* b_d2o    = (const float*)d_in[21];
    const float* w_d2     = (const float*)d_in[22];
    const float* b_d2     = (const float*)d_in[23];
    const float* w_up2    = (const float*)d_in[24];
    const float* b_up2    = (const float*)d_in[25];
    float* outp = (float*)d_out;

    static float* fea2down = sym(g_fea2down);
    static float* fea1     = sym(g_fea1);
    static float* fea2     = sym(g_fea2);
    static float* up1      = sym(g_up1);
    static float* fea      = sym(g_fea);
    static float* off1     = sym(g_off1);
    static float* fea11    = sym(g_fea11);
    static float* rs2      = sym(g_rs2);
    static float* off2     = sym(g_off2);
    static float* fea2d    = sym(g_fea2d);
    static float* up2      = sym(g_up2);
    static float* wq1      = sym(g_wq1);
    static float* wq2      = sym(g_wq2);

    // Weight repacks first
    prep_wq_kernel<<<dim3((4 * C * 4 * C + 255) / 256), 256>>>(w_up1, wq1);
    prep_wq_kernel<<<dim3((4 * C * 4 * C + 255) / 256), 256>>>(w_up2, wq2);

    // 1) fea_2 = conv(cat, w_down1, s=2) : (B,128,128,128)   nchunk=4
    conv3x3_v6<2, 4><<<dim3(W2 / 32, H2 / 8, B * 4), 128>>>(
        dem, rs, C, 2 * C, w_down1, b_down1, fea2down, 2 * C, H1, W1, H2, W2);

    // 2) fea_1 = conv(cat, w_c1, s=1) : (B,64,256,256)       nchunk=2
    conv3x3_v6<1, 8><<<dim3(W1 / 32, H1 / 8, B * 2), 128>>>(
        dem, rs, C, 2 * C, w_c1, b_c1, fea1, C, H1, W1, H1, W1);

    // 3) fea_2 = conv(fea_2, w_c12, s=1) : (B,64,128,128)    nchunk=2
    conv3x3_v6<1, 8><<<dim3(W2 / 32, H2 / 8, B * 2), 128>>>(
        fea2down, fea2down, 2 * C, 2 * C, w_c12, b_c12, fea2, C, H2, W2, H2, W2);

    // 4) fea_2_1 = convT(fea_2, w_up1) : (B,64,256,256)
    convt_v2<8><<<dim3(W2 / 32, H2 / 8, B * 8), 128>>>(fea2, wq1, b_up1, up1, H2, W2);

    // 5) fea = 1x1 conv(fea_1 + fea_2_1, w_off)
    conv1x1_add_kernel<<<dim3((H1 * W1) / 256, B), 256>>>(fea1, up1, w_off, b_off, fea, H1 * W1);

    // 6) offsets level 1 = conv(fea, w_d1o) : (B,18,256,256)
    conv3x3_kernel<1, 20><<<dim3(W1 / 32, H1 / 8, B), 256>>>(
        fea, fea, C, C, w_d1o, b_d1o, off1, 18, H1, W1, H1, W1);

    // 7) fea_1_1 = deform(rs, off1, w_d1)
    deform_db<<<dim3(W1 / 32, H1 / 8, B), 256>>>(rs, off1, w_d1, b_d1, fea11, H1, W1);

    // 8) rs_2 = conv(rs, w_downrs, s=2) : (B,64,128,128)     nchunk=2
    conv3x3_v6<2, 4><<<dim3(W2 / 32, H2 / 8, B * 2), 128>>>(
        rs, rs, C, C, w_downrs, b_downrs, rs2, C, H1, W1, H2, W2);

    // 9) offsets level 2 = conv(fea_2, w_d2o) : (B,18,128,128)
    conv3x3_kernel<1, 20><<<dim3(W2 / 32, H2 / 8, B), 256>>>(
        fea2, fea2, C, C, w_d2o, b_d2o, off2, 18, H2, W2, H2, W2);

    // 10) fea_2 = deform(rs_2, off2, w_d2)
    deform_db<<<dim3(W2 / 32, H2 / 8, B), 256>>>(rs2, off2, w_d2, b_d2, fea2d, H2, W2);

    // 11) fea_2_1 = convT(fea_2, w_up2) : (B,64,256,256)
    convt_v2<8><<<dim3(W2 / 32, H2 / 8, B * 8), 128>>>(fea2d, wq2, b_up2, up2, H2, W2);

    // 12) out = 1x1 conv(fea_1_1 + fea_2_1, w_c3)
    conv1x1_add_kernel<<<dim3((H1 * W1) / 256, B), 256>>>(fea11, up2, w_c3, b_c3, outp, H1 * W1);
}

// round 13
// speedup vs baseline: 1.0190x; 1.0190x over previous
#include <cuda_runtime.h>
#include <cstdint>
#include <cstring>

static constexpr int B  = 2;
static constexpr int C  = 64;
static constexpr int H1 = 256, W1 = 256;
static constexpr int H2 = 128, W2 = 128;

// ---------------------------------------------------------------------------
// Packed f32x2 helpers
// ---------------------------------------------------------------------------
__device__ __forceinline__ unsigned long long pack2(float x)
{
    unsigned long long r;
    asm("mov.b64 %0, {%1, %1};" : "=l"(r) : "f"(x));
    return r;
}
__device__ __forceinline__ unsigned long long pack_pair(float lo, float hi)
{
    unsigned long long r;
    asm("mov.b64 %0, {%1, %2};" : "=l"(r) : "f"(lo), "f"(hi));
    return r;
}
__device__ __forceinline__ void fma2(unsigned long long& acc,
                                     unsigned long long a, unsigned long long b)
{
    asm("fma.rn.f32x2 %0, %1, %2, %0;" : "+l"(acc) : "l"(a), "l"(b));
}
__device__ __forceinline__ float2 unpack2(unsigned long long v)
{
    float2 r;
    asm("mov.b64 {%0, %1}, %2;" : "=f"(r.x), "=f"(r.y) : "l"(v));
    return r;
}
__device__ __forceinline__ unsigned long long f2_as_ull(float2 v)
{
    unsigned long long r;
    memcpy(&r, &v, 8);
    return r;
}

// ---------------------------------------------------------------------------
// cp.async helpers
// ---------------------------------------------------------------------------
__device__ __forceinline__ void cp_async4(uint32_t dst_smem, const float* src, bool valid)
{
    int sz = valid ? 4 : 0;
    asm volatile("cp.async.ca.shared.global [%0], [%1], 4, %2;"
                 :: "r"(dst_smem), "l"(src), "r"(sz));
}
__device__ __forceinline__ void cp_async8(uint32_t dst_smem, const unsigned long long* src)
{
    asm volatile("cp.async.ca.shared.global [%0], [%1], 8;"
                 :: "r"(dst_smem), "l"(src));
}
__device__ __forceinline__ void cp_commit() { asm volatile("cp.async.commit_group;"); }
__device__ __forceinline__ void cp_wait0()  { asm volatile("cp.async.wait_group 0;"); }
__device__ __forceinline__ uint32_t smem_u32(const void* p)
{
    return (uint32_t)__cvta_generic_to_shared(p);
}

// ---------------------------------------------------------------------------
// Device scratch
// ---------------------------------------------------------------------------
__device__ float g_fea2down[B * 128 * H2 * W2];
__device__ float g_fea1    [B * C   * H1 * W1];
__device__ float g_fea2    [B * C   * H2 * W2];
__device__ float g_up1     [B * C   * H1 * W1];
__device__ float g_fea     [B * C   * H1 * W1];
__device__ float g_off1    [B * 18  * H1 * W1];
__device__ float g_fea11   [B * C   * H1 * W1];
__device__ float g_rs2     [B * C   * H2 * W2];
__device__ float g_off2    [B * 18  * H2 * W2];
__device__ float g_fea2d   [B * C   * H2 * W2];
__device__ float g_up2     [B * C   * H1 * W1];
__device__ float g_wq1     [4 * C * 4 * C];
__device__ float g_wq2     [4 * C * 4 * C];
// duplicated-weight scratch for stride-1 convs: [ci][tap][o] -> (w,w)
__device__ unsigned long long g_wd_c1 [128 * 9 * 64];
__device__ unsigned long long g_wd_c12[128 * 9 * 64];

// ---------------------------------------------------------------------------
// Weight duplication prep: wd[(ci*9+tap)*Cout+o] = (w,w) from w[(o,ci,tap)]
// ---------------------------------------------------------------------------
__global__ void prep_wdup_kernel(const float* __restrict__ w,
                                 unsigned long long* __restrict__ wd,
                                 int Cin, int Cout)
{
    int idx = blockIdx.x * 256 + threadIdx.x;
    if (idx >= Cin * 9 * Cout) return;
    int o   = idx % Cout;
    int tap = (idx / Cout) % 9;
    int ci  = idx / (9 * Cout);
    float v = w[((size_t)o * Cin + ci) * 9 + tap];
    unsigned int u = __float_as_uint(v);
    wd[idx] = ((unsigned long long)u << 32) | u;
}

// ---------------------------------------------------------------------------
// conv3x3 v7 (STRIDE 1 ONLY): block = 32 cols x 8 rows x 32 out-ch.
// 128 threads: colg=tid&3 (8-col group), row=(tid>>2)&7, cog=tid>>5.
// Each thread: 8 adjacent pixels x 8 channels as 4 f32x2 pixel-pairs/channel.
// Weights from pre-duplicated GMEM via cp.async8 -> LDS.64 broadcast (no movs).
// Activations via aligned float2 LDS.64; only kw=1 needs pack_pair.
// Requires Cout % 32 == 0, Ho % 8 == 0, Wo % 32 == 0, Cin % CI_BLK == 0.
// ---------------------------------------------------------------------------
template <int CI_BLK>
__global__ __launch_bounds__(128, 4)
void conv3x3_v7(const float* __restrict__ inA, const float* __restrict__ inB,
                int C0, int Cin,
                const unsigned long long* __restrict__ wdup,
                const float* __restrict__ bias,
                float* __restrict__ out, int Cout,
                int H, int W, int Ho, int Wo)
{
    constexpr int XR = 10;                  // input rows
    constexpr int XC = 34;                  // input cols
    constexpr int XP = 36;                  // pitch (even -> 8B alignment)
    __shared__ __align__(16) float xs[2][CI_BLK][XR * XP];
    __shared__ __align__(16) unsigned long long w_d[2][CI_BLK][9][32];

    const int tid  = threadIdx.x;
    const int colg = tid & 3;
    const int row  = (tid >> 2) & 7;
    const int cog  = tid >> 5;
    const int col0 = colg * 8;
    const int nchunk = Cout >> 5;
    const int b     = blockIdx.z / nchunk;
    const int chunk = blockIdx.z % nchunk;
    const int co_base = chunk * 32;
    const int ow0 = blockIdx.x * 32;
    const int oh0 = blockIdx.y * 8;
    const int HW = H * W;

    unsigned long long acc[8][4];
#pragma unroll
    for (int co = 0; co < 8; co++)
#pragma unroll
        for (int j = 0; j < 4; j++) acc[co][j] = 0ull;

    auto stage = [&](int sb, int cb) {
        for (int i = tid; i < CI_BLK * XR * XC; i += 128) {
            int ci  = i / (XR * XC);
            int rem = i % (XR * XC);
            int lr = rem / XC, lc = rem % XC;
            int r = oh0 - 1 + lr;
            int c = ow0 - 1 + lc;
            int cig = cb + ci;
            const float* src = (cig < C0)
                ? (inA + ((size_t)b * C0 + cig) * HW)
                : (inB + ((size_t)b * (Cin - C0) + (cig - C0)) * HW);
            bool valid = (r >= 0 && r < H && c >= 0 && c < W);
            cp_async4(smem_u32(&xs[sb][ci][lr * XP + lc]),
                      src + (valid ? r * W + c : 0), valid);
        }
        for (int i = tid; i < CI_BLK * 9 * 32; i += 128) {
            int o = i & 31, tap = (i >> 5) % 9, ci = i / 288;
            cp_async8(smem_u32(&w_d[sb][ci][tap][o]),
                      wdup + ((size_t)(cb + ci) * 9 + tap) * Cout + co_base + o);
        }
        cp_commit();
    };

    stage(0, 0);
    const int nst = Cin / CI_BLK;
    for (int s = 0; s < nst; s++) {
        cp_wait0();
        __syncthreads();
        if (s + 1 < nst) stage((s + 1) & 1, (s + 1) * CI_BLK);
        const int sb = s & 1;

        for (int ci = 0; ci < CI_BLK; ci++) {
            const float* xc = xs[sb][ci];
            const unsigned long long (*wt)[32] = w_d[sb][ci];
#pragma unroll
            for (int kh = 0; kh < 3; kh++) {
                float2 f[5];
                {
                    const float2* xr = (const float2*)(xc + (row + kh) * XP + col0);
#pragma unroll
                    for (int j = 0; j < 5; j++) f[j] = xr[j];
                }
                unsigned long long a0[4], a1[4], a2[4];
#pragma unroll
                for (int j = 0; j < 4; j++) {
                    a0[j] = f2_as_ull(f[j]);
                    a2[j] = f2_as_ull(f[j + 1]);
                    a1[j] = pack_pair(f[j].y, f[j + 1].x);
                }
                // kw = 0
                {
                    const unsigned long long* wp = wt[kh * 3 + 0] + cog * 8;
#pragma unroll
                    for (int co = 0; co < 8; co++) {
                        unsigned long long ww = wp[co];
                        fma2(acc[co][0], a0[0], ww);
                        fma2(acc[co][1], a0[1], ww);
                        fma2(acc[co][2], a0[2], ww);
                        fma2(acc[co][3], a0[3], ww);
                    }
                }
                // kw = 1
                {
                    const unsigned long long* wp = wt[kh * 3 + 1] + cog * 8;
#pragma unroll
                    for (int co = 0; co < 8; co++) {
                        unsigned long long ww = wp[co];
                        fma2(acc[co][0], a1[0], ww);
                        fma2(acc[co][1], a1[1], ww);
                        fma2(acc[co][2], a1[2], ww);
                        fma2(acc[co][3], a1[3], ww);
                    }
                }
                // kw = 2
                {
                    const unsigned long long* wp = wt[kh * 3 + 2] + cog * 8;
#pragma unroll
                    for (int co = 0; co < 8; co++) {
                        unsigned long long ww = wp[co];
                        fma2(acc[co][0], a2[0], ww);
                        fma2(acc[co][1], a2[1], ww);
                        fma2(acc[co][2], a2[2], ww);
                        fma2(acc[co][3], a2[3], ww);
                    }
                }
            }
        }
    }

    const int oh = oh0 + row;
#pragma unroll
    for (int co = 0; co < 8; co++) {
        int og = co_base + cog * 8 + co;
        float bv = bias[og];
        float* op = out + (((size_t)b * Cout + og) * Ho + oh) * Wo + ow0 + col0;
#pragma unroll
        for (int j = 0; j < 4; j++) {
            float2 v = unpack2(acc[co][j]);
            op[2 * j]     = v.x + bv;
            op[2 * j + 1] = v.y + bv;
        }
    }
}

// ---------------------------------------------------------------------------
// conv3x3 v5 (R11 proven, used for STRIDE 2): 16x16 tile, 2 px/thread,
// 32 out-ch chunk, cp.async double-buffered.
// ---------------------------------------------------------------------------
template <int STRIDE, int CI_BLK>
__global__ __launch_bounds__(128, 4)
void conv3x3_v5(const float* __restrict__ inA, const float* __restrict__ inB,
                int C0, int Cin,
                const float* __restrict__ w, const float* __restrict__ bias,
                float* __restrict__ out, int Cout,
                int H, int W, int Ho, int Wo)
{
    constexpr int XR = 15 * STRIDE + 3;
    constexpr int XC = 15 * STRIDE + 3;
    constexpr int XP = XC + (STRIDE == 1 ? 1 : 2);
    __shared__ __align__(16) float xs[2][CI_BLK][XR * XP];
    __shared__ __align__(16) float w_s[2][CI_BLK][9][32];

    const int tid = threadIdx.x;
    const int tx = tid & 15, ty = tid >> 4;
    const int nchunk = Cout >> 5;
    const int b     = blockIdx.z / nchunk;
    const int chunk = blockIdx.z % nchunk;
    const int co_base = chunk * 32;
    const int ow0 = blockIdx.x * 16;
    const int oh0 = blockIdx.y * 16;
    const int HW = H * W;

    unsigned long long acc[2][16];
#pragma unroll
    for (int a = 0; a < 2; a++)
#pragma unroll
        for (int o = 0; o < 16; o++) acc[a][o] = 0ull;

    auto stage = [&](int sb, int cb) {
        for (int i = tid; i < CI_BLK * XR * XC; i += 128) {
            int ci  = i / (XR * XC);
            int rem = i % (XR * XC);
            int lr = rem / XC, lc = rem % XC;
            int r = oh0 * STRIDE - 1 + lr;
            int c = ow0 * STRIDE - 1 + lc;
            int cig = cb + ci;
            const float* src = (cig < C0)
                ? (inA + ((size_t)b * C0 + cig) * HW)
                : (inB + ((size_t)b * (Cin - C0) + (cig - C0)) * HW);
            bool valid = (r >= 0 && r < H && c >= 0 && c < W);
            cp_async4(smem_u32(&xs[sb][ci][lr * XP + lc]),
                      src + (valid ? r * W + c : 0), valid);
        }
        for (int i = tid; i < CI_BLK * 9 * 32; i += 128) {
            int o = i & 31, tap = (i >> 5) % 9, ci = i / 288;
            cp_async4(smem_u32(&w_s[sb][ci][tap][o]),
                      w + ((size_t)(co_base + o) * Cin + cb + ci) * 9 + tap, true);
        }
        cp_commit();
    };

    stage(0, 0);
    const int nst = Cin / CI_BLK;
    for (int s = 0; s < nst; s++) {
        cp_wait0();
        __syncthreads();
        if (s + 1 < nst) stage((s + 1) & 1, (s + 1) * CI_BLK);
        const int sb = s & 1;

        for (int ci = 0; ci < CI_BLK; ci++) {
            const float* xc = xs[sb][ci];
#pragma unroll
            for (int kh = 0; kh < 3; kh++) {
                float xv[2][3];
#pragma unroll
                for (int a = 0; a < 2; a++) {
                    int rrow = (ty + 8 * a) * STRIDE + kh;
                    int ccol = tx * STRIDE;
#pragma unroll
                    for (int kw = 0; kw < 3; kw++)
                        xv[a][kw] = xc[rrow * XP + ccol + kw];
                }
#pragma unroll
                for (int kw = 0; kw < 3; kw++) {
                    unsigned long long xx0 = pack2(xv[0][kw]);
                    unsigned long long xx1 = pack2(xv[1][kw]);
                    const ulonglong2* w2 = (const ulonglong2*)w_s[sb][ci][kh * 3 + kw];
#pragma unroll
                    for (int o8 = 0; o8 < 8; o8++) {
                        ulonglong2 wv = w2[o8];
                        fma2(acc[0][o8 * 2 + 0], xx0, wv.x);
                        fma2(acc[0][o8 * 2 + 1], xx0, wv.y);
                        fma2(acc[1][o8 * 2 + 0], xx1, wv.x);
                        fma2(acc[1][o8 * 2 + 1], xx1, wv.y);
                    }
                }
            }
        }
    }

#pragma unroll
    for (int a = 0; a < 2; a++) {
        int oh = oh0 + ty + 8 * a;
        int ow = ow0 + tx;
#pragma unroll
        for (int o2 = 0; o2 < 16; o2++) {
            float2 v = unpack2(acc[a][o2]);
            int og = co_base + 2 * o2;
            out[(((size_t)b * Cout + og) * Ho + oh) * Wo + ow]     = v.x + bias[og];
            out[(((size_t)b * Cout + og + 1) * Ho + oh) * Wo + ow] = v.y + bias[og + 1];
        }
    }
}

// ---------------------------------------------------------------------------
// Old-style 3x3 conv for the offset heads (Cout=18, CO=20 register block).
// ---------------------------------------------------------------------------
template <int STRIDE, int CO>
__global__ __launch_bounds__(256)
void conv3x3_kernel(const float* __restrict__ inA, const float* __restrict__ inB,
                    int C0, int Cin,
                    const float* __restrict__ w, const float* __restrict__ bias,
                    float* __restrict__ out, int Cout,
                    int H, int W, int Ho, int Wo)
{
    constexpr int XR = 7 * STRIDE + 3;
    constexpr int XC = 31 * STRIDE + 3;
    constexpr int XP = XC + (STRIDE == 2 ? 1 : 0);
    __shared__ __align__(16) float xs[XR * XP];
    __shared__ __align__(16) float w_s[9 * CO];

    const int tid = threadIdx.x;
    const int tx = tid & 31, ty = tid >> 5;
    const int nchunk = (Cout + CO - 1) / CO;
    const int b     = blockIdx.z / nchunk;
    const int chunk = blockIdx.z % nchunk;
    const int co_base = chunk * CO;
    const int ow0 = blockIdx.x * 32;
    const int oh0 = blockIdx.y * 8;
    const int HW = H * W;

    unsigned long long acc[CO / 2];
#pragma unroll
    for (int o = 0; o < CO / 2; o++) acc[o] = 0ull;

    for (int ci = 0; ci < Cin; ci++) {
        const float* src = (ci < C0)
            ? (inA + ((size_t)b * C0 + ci) * HW)
            : (inB + ((size_t)b * (Cin - C0) + (ci - C0)) * HW);
        __syncthreads();
        for (int i = tid; i < XR * XC; i += 256) {
            int lr = i / XC, lc = i % XC;
            int r = oh0 * STRIDE - 1 + lr;
            int c = ow0 * STRIDE - 1 + lc;
            xs[lr * XP + lc] = (r >= 0 && r < H && c >= 0 && c < W) ? src[r * W + c] : 0.f;
        }
        for (int i = tid; i < 9 * CO; i += 256) {
            int tap = i / CO, o = i % CO;
            int og = co_base + o;
            w_s[tap * CO + o] = (og < Cout) ? w[((size_t)og * Cin + ci) * 9 + tap] : 0.f;
        }
        __syncthreads();

        float xv[9];
#pragma unroll
        for (int kh = 0; kh < 3; kh++)
#pragma unroll
            for (int kw = 0; kw < 3; kw++)
                xv[kh * 3 + kw] = xs[(ty * STRIDE + kh) * XP + tx * STRIDE + kw];

#pragma unroll
        for (int tap = 0; tap < 9; tap++) {
            unsigned long long xx = pack2(xv[tap]);
            const ulonglong2* w2 = (const ulonglong2*)(w_s + tap * CO);
#pragma unroll
            for (int o4 = 0; o4 < CO / 4; o4++) {
                ulonglong2 wv = w2[o4];
                fma2(acc[o4 * 2 + 0], xx, wv.x);
                fma2(acc[o4 * 2 + 1], xx, wv.y);
            }
        }
    }

    const int oh = oh0 + ty, ow = ow0 + tx;
    if (oh < Ho && ow < Wo) {
#pragma unroll
        for (int o2 = 0; o2 < CO / 2; o2++) {
            float2 v = unpack2(acc[o2]);
            int og0 = co_base + 2 * o2;
            if (og0 < Cout)
                out[(((size_t)b * Cout + og0) * Ho + oh) * Wo + ow] = v.x + bias[og0];
            if (og0 + 1 < Cout)
                out[(((size_t)b * Cout + og0 + 1) * Ho + oh) * Wo + ow] = v.y + bias[og0 + 1];
        }
    }
}

// ---------------------------------------------------------------------------
// Weight repack for transposed conv (4x4, stride 2, pad 1).
// ---------------------------------------------------------------------------
__global__ void prep_wq_kernel(const float* __restrict__ w, float* __restrict__ wq)
{
    int idx = blockIdx.x * 256 + threadIdx.x;
    if (idx >= 4 * C * 4 * C) return;
    int o  = idx & 63;
    int t  = (idx >> 6) & 3;
    int ci = (idx >> 8) & 63;
    int pc = idx >> 14;
    int pa = pc >> 1, pb = pc & 1;
    int di = t >> 1, dj = t & 1;
    int kh = 3 - pa - 2 * di;
    int kw = 3 - pb - 2 * dj;
    wq[idx] = w[((ci * C + o) * 4 + kh) * 4 + kw];
}

// ---------------------------------------------------------------------------
// convt v2: 128 threads, 2 px/thread, 32 out-ch per z-slice, 8-ch ci chunks.
// ---------------------------------------------------------------------------
template <int CI_BLK>
__global__ __launch_bounds__(128)
void convt_v2(const float* __restrict__ in, const float* __restrict__ wq,
              const float* __restrict__ bias, float* __restrict__ out,
              int Hin, int Win)
{
    __shared__ __align__(16) float xs[CI_BLK][9 * 35];
    __shared__ __align__(16) float w_s[CI_BLK][4][32];

    const int tid = threadIdx.x;
    const int tx = tid & 15, ty = tid >> 4;
    const int zc = blockIdx.z;
    const int b   = zc >> 3;
    const int pc  = (zc >> 1) & 3;
    const int coh = zc & 1;
    const int co_base = coh * 32;
    const int pa = pc >> 1, pb = pc & 1;
    const int j0 = blockIdx.x * 32;
    const int i0 = blockIdx.y * 8;
    const int HWin = Hin * Win;
    const float* inb = in + (size_t)b * C * HWin;

    unsigned long long acc[2][16];
#pragma unroll
    for (int bb = 0; bb < 2; bb++)
#pragma unroll
        for (int o = 0; o < 16; o++) acc[bb][o] = 0ull;

    for (int cb = 0; cb < C; cb += CI_BLK) {
        __syncthreads();
        for (int i = tid; i < CI_BLK * 9 * 34; i += 128) {
            int ci = i / (9 * 34);
            int rem = i % (9 * 34);
            int lr = rem / 34, lc = rem % 34;
            int r = i0 + pa - 1 + lr;
            int c = j0 + pb - 1 + lc;
            xs[ci][lr * 35 + lc] =
                (r >= 0 && r < Hin && c >= 0 && c < Win) ? inb[(size_t)(cb + ci) * HWin + r * Win + c] : 0.f;
        }
        for (int i = tid; i < CI_BLK * 4 * 32; i += 128) {
            int o = i & 31, t = (i >> 5) & 3, ci = i >> 7;
            w_s[ci][t][o] = wq[(size_t)pc * (C * 4 * C) + (cb + ci) * (4 * C) + t * C + co_base + o];
        }
        __syncthreads();

        for (int ci = 0; ci < CI_BLK; ci++) {
            const float* xc = xs[ci];
            float xv[2][2][2];
#pragma unroll
            for (int di = 0; di < 2; di++)
#pragma unroll
                for (int bb = 0; bb < 2; bb++)
#pragma unroll
                    for (int dj = 0; dj < 2; dj++)
                        xv[di][bb][dj] = xc[(ty + di) * 35 + tx + 16 * bb + dj];

#pragma unroll
            for (int t = 0; t < 4; t++) {
                int di = t >> 1, dj = t & 1;
                unsigned long long xx[2];
                xx[0] = pack2(xv[di][0][dj]);
                xx[1] = pack2(xv[di][1][dj]);
                const ulonglong2* w2 = (const ulonglong2*)w_s[ci][t];
#pragma unroll
                for (int o8 = 0; o8 < 8; o8++) {
                    ulonglong2 wv = w2[o8];
#pragma unroll
                    for (int bb = 0; bb < 2; bb++) {
                        fma2(acc[bb][o8 * 2 + 0], xx[bb], wv.x);
                        fma2(acc[bb][o8 * 2 + 1], xx[bb], wv.y);
                    }
                }
            }
        }
    }

    const int Hout = 2 * Hin, Wout = 2 * Win;
    const int oh = 2 * (i0 + ty) + pa;
#pragma unroll
    for (int bb = 0; bb < 2; bb++) {
        int ow = 2 * (j0 + tx + 16 * bb) + pb;
#pragma unroll
        for (int o2 = 0; o2 < 16; o2++) {
            float2 v = unpack2(acc[bb][o2]);
            int og = co_base + 2 * o2;
            out[(((size_t)b * C + og) * Hout + oh) * Wout + ow]     = v.x + bias[og];
            out[(((size_t)b * C + og + 1) * Hout + oh) * Wout + ow] = v.y + bias[og + 1];
        }
    }
}

// ---------------------------------------------------------------------------
// 1x1 conv over (a + b2), C->C (256 threads, 1 px, 64 acc regs).
// ---------------------------------------------------------------------------
__global__ __launch_bounds__(256)
void conv1x1_add_kernel(const float* __restrict__ a, const float* __restrict__ b2,
                        const float* __restrict__ w, const float* __restrict__ bias,
                        float* __restrict__ out, int HW)
{
    __shared__ __align__(16) float w_s[C * C];   // [ci][o]
    const int tid = threadIdx.x;
    for (int i = tid; i < C * C; i += 256) {
        int ci = i >> 6, o = i & 63;
        w_s[i] = w[o * C + ci];
    }
    __syncthreads();

    const int pix = blockIdx.x * 256 + tid;
    const int b = blockIdx.y;
    if (pix >= HW) return;
    const float* ab = a  + (size_t)b * C * HW + pix;
    const float* bb = b2 + (size_t)b * C * HW + pix;

    unsigned long long acc[C / 2];
#pragma unroll
    for (int o = 0; o < C / 2; o++) acc[o] = 0ull;

    for (int ci = 0; ci < C; ci++) {
        unsigned long long xx = pack2(ab[(size_t)ci * HW] + bb[(size_t)ci * HW]);
        const ulonglong2* w2 = (const ulonglong2*)(w_s + ci * C);
#pragma unroll
        for (int o4 = 0; o4 < C / 4; o4++) {
            ulonglong2 wv = w2[o4];
            fma2(acc[o4 * 2 + 0], xx, wv.x);
            fma2(acc[o4 * 2 + 1], xx, wv.y);
        }
    }
    float* ob = out + (size_t)b * C * HW + pix;
#pragma unroll
    for (int o2 = 0; o2 < C / 2; o2++) {
        float2 v = unpack2(acc[o2]);
        ob[(size_t)(2 * o2) * HW]     = v.x + bias[2 * o2];
        ob[(size_t)(2 * o2 + 1) * HW] = v.y + bias[2 * o2 + 1];
    }
}

// ---------------------------------------------------------------------------
// Deformable conv (256 threads, 1 px, 64 acc regs) with cp.async
// double-buffered per-tap weight staging. Reference-exact.
// ---------------------------------------------------------------------------
__global__ __launch_bounds__(256)
void deform_db(const float* __restrict__ x, const float* __restrict__ off,
               const float* __restrict__ w, const float* __restrict__ bias,
               float* __restrict__ out, int H, int W)
{
    __shared__ __align__(16) float w_s[2][C * C];   // [c][o], double-buffered
    const int tid = threadIdx.x;
    const int tx = tid & 31, ty = tid >> 5;
    const int ow = blockIdx.x * 32 + tx;
    const int oh = blockIdx.y * 8 + ty;
    const int b  = blockIdx.z;
    const int HW = H * W;
    const float* xb   = x   + (size_t)b * C * HW;
    const float* offb = off + (size_t)b * 18 * HW;
    const int pix = oh * W + ow;

    unsigned long long acc[C / 2];
#pragma unroll
    for (int o = 0; o < C / 2; o++) acc[o] = 0ull;

    const float rmax = (float)(H + 1);
    const float cmax = (float)(W + 1);

    auto stage = [&](int sb, int n) {
        for (int i = tid; i < C * C; i += 256) {
            int c = i >> 6, o = i & 63;
            cp_async4(smem_u32(&w_s[sb][i]), w + (size_t)o * (C * 9) + c * 9 + n, true);
        }
        cp_commit();
    };

    stage(0, 0);
    for (int n = 0; n < 9; n++) {
        cp_wait0();
        __syncthreads();
        if (n + 1 < 9) stage((n + 1) & 1, n + 1);
        const float* ws = w_s[n & 1];

        float offr = offb[(size_t)n * HW + pix];
        float offc = offb[(size_t)(9 + n) * HW + pix];
        float pr  = (float)(oh + (n / 3)) + offr;
        float pcc = (float)(ow + (n % 3)) + offc;
        pr  = fminf(fmaxf(pr, 0.f), rmax);
        pcc = fminf(fmaxf(pcc, 0.f), cmax);
        float r0f = floorf(pr), c0f = floorf(pcc);
        int r0 = (int)r0f, c0 = (int)c0f;
        int r1 = min(r0 + 1, H + 1), c1 = min(c0 + 1, W + 1);
        float fr = pr - r0f, fc = pcc - c0f;
        float w00 = (1.f - fr) * (1.f - fc);
        float w01 = (1.f - fr) * fc;
        float w10 = fr * (1.f - fc);
        float w11 = fr * fc;

        int rr0 = r0 - 1, rr1 = r1 - 1, cc0 = c0 - 1, cc1 = c1 - 1;
        bool vr0 = (rr0 >= 0) && (rr0 < H);
        bool vr1 = (rr1 >= 0) && (rr1 < H);
        bool vc0 = (cc0 >= 0) && (cc0 < W);
        bool vc1 = (cc1 >= 0) && (cc1 < W);
        float m00 = (vr0 && vc0) ? w00 : 0.f;
        float m01 = (vr0 && vc1) ? w01 : 0.f;
        float m10 = (vr1 && vc0) ? w10 : 0.f;
        float m11 = (vr1 && vc1) ? w11 : 0.f;
        int sr0 = vr0 ? rr0 : 0, sr1 = vr1 ? rr1 : 0;
        int sc0 = vc0 ? cc0 : 0, sc1 = vc1 ? cc1 : 0;
        int i00 = sr0 * W + sc0;
        int i01 = sr0 * W + sc1;
        int i10 = sr1 * W + sc0;
        int i11 = sr1 * W + sc1;

        for (int c = 0; c < C; c++) {
            const float* xc = xb + (size_t)c * HW;
            float v = m00 * xc[i00] + m01 * xc[i01] + m10 * xc[i10] + m11 * xc[i11];
            unsigned long long vv = pack2(v);
            const ulonglong2* w2 = (const ulonglong2*)(ws + c * C);
#pragma unroll
            for (int o4 = 0; o4 < C / 4; o4++) {
                ulonglong2 wv = w2[o4];
                fma2(acc[o4 * 2 + 0], vv, wv.x);
                fma2(acc[o4 * 2 + 1], vv, wv.y);
            }
        }
    }

    if (oh < H && ow < W) {
#pragma unroll
        for (int o2 = 0; o2 < C / 2; o2++) {
            float2 v = unpack2(acc[o2]);
            out[(((size_t)b * C + 2 * o2) * H + oh) * W + ow]     = v.x + bias[2 * o2];
            out[(((size_t)b * C + 2 * o2 + 1) * H + oh) * W + ow] = v.y + bias[2 * o2 + 1];
        }
    }
}

// ---------------------------------------------------------------------------
// Launch
// ---------------------------------------------------------------------------
static float* sym(const void* s)
{
    void* p = nullptr;
    cudaGetSymbolAddress(&p, s);
    return (float*)p;
}

extern "C" void kernel_launch(void* const* d_in, const int* in_sizes, int n_in,
                              void* d_out, int out_size)
{
    const float* dem      = (const float*)d_in[0];
    const float* rs       = (const float*)d_in[1];
    const float* w_down1  = (const float*)d_in[2];
    const float* b_down1  = (const float*)d_in[3];
    const float* w_c1     = (const float*)d_in[4];
    const float* b_c1     = (const float*)d_in[5];
    const float* w_c12    = (const float*)d_in[6];
    const float* b_c12    = (const float*)d_in[7];
    const float* w_up1    = (const float*)d_in[8];
    const float* b_up1    = (const float*)d_in[9];
    const float* w_downrs = (const float*)d_in[10];
    const float* b_downrs = (const float*)d_in[11];
    const float* w_off    = (const float*)d_in[12];
    const float* b_off    = (const float*)d_in[13];
    const float* w_c3     = (const float*)d_in[14];
    const float* b_c3     = (const float*)d_in[15];
    const float* w_d1o    = (const float*)d_in[16];
    const float* b_d1o    = (const float*)d_in[17];
    const float* w_d1     = (const float*)d_in[18];
    const float* b_d1     = (const float*)d_in[19];
    const float* w_d2o    = (const float*)d_in[20];
    const float* b_d2o    = (const float*)d_in[21];
    const float* w_d2     = (const float*)d_in[22];
    const float* b_d2     = (const float*)d_in[23];
    const float* w_up2    = (const float*)d_in[24];
    const float* b_up2    = (const float*)d_in[25];
    float* outp = (float*)d_out;

    static float* fea2down = sym(g_fea2down);
    static float* fea1     = sym(g_fea1);
    static float* fea2     = sym(g_fea2);
    static float* up1      = sym(g_up1);
    static float* fea      = sym(g_fea);
    static float* off1     = sym(g_off1);
    static float* fea11    = sym(g_fea11);
    static float* rs2      = sym(g_rs2);
    static float* off2     = sym(g_off2);
    static float* fea2d    = sym(g_fea2d);
    static float* up2      = sym(g_up2);
    static float* wq1      = sym(g_wq1);
    static float* wq2      = sym(g_wq2);
    static unsigned long long* wd_c1  = (unsigned long long*)sym(g_wd_c1);
    static unsigned long long* wd_c12 = (unsigned long long*)sym(g_wd_c12);

    // Weight repacks first
    prep_wq_kernel<<<dim3((4 * C * 4 * C + 255) / 256), 256>>>(w_up1, wq1);
    prep_wq_kernel<<<dim3((4 * C * 4 * C + 255) / 256), 256>>>(w_up2, wq2);
    prep_wdup_kernel<<<dim3((128 * 9 * 64 + 255) / 256), 256>>>(w_c1, wd_c1, 2 * C, C);
    prep_wdup_kernel<<<dim3((128 * 9 * 64 + 255) / 256), 256>>>(w_c12, wd_c12, 2 * C, C);

    // 1) fea_2 = conv(cat, w_down1, s=2) : (B,128,128,128)   v5, nchunk=4
    conv3x3_v5<2, 4><<<dim3(W2 / 16, H2 / 16, B * 4), 128>>>(
        dem, rs, C, 2 * C, w_down1, b_down1, fea2down, 2 * C, H1, W1, H2, W2);

    // 2) fea_1 = conv(cat, w_c1, s=1) : (B,64,256,256)       v7, nchunk=2
    conv3x3_v7<4><<<dim3(W1 / 32, H1 / 8, B * 2), 128>>>(
        dem, rs, C, 2 * C, wd_c1, b_c1, fea1, C, H1, W1, H1, W1);

    // 3) fea_2 = conv(fea_2, w_c12, s=1) : (B,64,128,128)    v7, nchunk=2
    conv3x3_v7<4><<<dim3(W2 / 32, H2 / 8, B * 2), 128>>>(
        fea2down, fea2down, 2 * C, 2 * C, wd_c12, b_c12, fea2, C, H2, W2, H2, W2);

    // 4) fea_2_1 = convT(fea_2, w_up1) : (B,64,256,256)
    convt_v2<8><<<dim3(W2 / 32, H2 / 8, B * 8), 128>>>(fea2, wq1, b_up1, up1, H2, W2);

    // 5) fea = 1x1 conv(fea_1 + fea_2_1, w_off)
    conv1x1_add_kernel<<<dim3((H1 * W1) / 256, B), 256>>>(fea1, up1, w_off, b_off, fea, H1 * W1);

    // 6) offsets level 1 = conv(fea, w_d1o) : (B,18,256,256)
    conv3x3_kernel<1, 20><<<dim3(W1 / 32, H1 / 8, B), 256>>>(
        fea, fea, C, C, w_d1o, b_d1o, off1, 18, H1, W1, H1, W1);

    // 7) fea_1_1 = deform(rs, off1, w_d1)
    deform_db<<<dim3(W1 / 32, H1 / 8, B), 256>>>(rs, off1, w_d1, b_d1, fea11, H1, W1);

    // 8) rs_2 = conv(rs, w_downrs, s=2) : (B,64,128,128)     v5, nchunk=2
    conv3x3_v5<2, 4><<<dim3(W2 / 16, H2 / 16, B * 2), 128>>>(
        rs, rs, C, C, w_downrs, b_downrs, rs2, C, H1, W1, H2, W2);

    // 9) offsets level 2 = conv(fea_2, w_d2o) : (B,18,128,128)
    conv3x3_kernel<1, 20><<<dim3(W2 / 32, H2 / 8, B), 256>>>(
        fea2, fea2, C, C, w_d2o, b_d2o, off2, 18, H2, W2, H2, W2);

    // 10) fea_2 = deform(rs_2, off2, w_d2)
    deform_db<<<dim3(W2 / 32, H2 / 8, B), 256>>>(rs2, off2, w_d2, b_d2, fea2d, H2, W2);

    // 11) fea_2_1 = convT(fea_2, w_up2) : (B,64,256,256)
    convt_v2<8><<<dim3(W2 / 32, H2 / 8, B * 8), 128>>>(fea2d, wq2, b_up2, up2, H2, W2);

    // 12) out = 1x1 conv(fea_1_1 + fea_2_1, w_c3)
    conv1x1_add_kernel<<<dim3((H1 * W1) / 256, B), 256>>>(fea11, up2, w_c3, b_c3, outp, H1 * W1);
}

// round 14
// speedup vs baseline: 1.0485x; 1.0289x over previous
#include <cuda_runtime.h>
#include <cstdint>
#include <cstring>

static constexpr int B  = 2;
static constexpr int C  = 64;
static constexpr int H1 = 256, W1 = 256;
static constexpr int H2 = 128, W2 = 128;

// ---------------------------------------------------------------------------
// Packed f32x2 helpers
// ---------------------------------------------------------------------------
__device__ __forceinline__ unsigned long long pack2(float x)
{
    unsigned long long r;
    asm("mov.b64 %0, {%1, %1};" : "=l"(r) : "f"(x));
    return r;
}
__device__ __forceinline__ unsigned long long pack_pair(float lo, float hi)
{
    unsigned long long r;
    asm("mov.b64 %0, {%1, %2};" : "=l"(r) : "f"(lo), "f"(hi));
    return r;
}
__device__ __forceinline__ void fma2(unsigned long long& acc,
                                     unsigned long long a, unsigned long long b)
{
    asm("fma.rn.f32x2 %0, %1, %2, %0;" : "+l"(acc) : "l"(a), "l"(b));
}
__device__ __forceinline__ float2 unpack2(unsigned long long v)
{
    float2 r;
    asm("mov.b64 {%0, %1}, %2;" : "=f"(r.x), "=f"(r.y) : "l"(v));
    return r;
}

// ---------------------------------------------------------------------------
// cp.async helpers (4-byte, zero-fill on invalid via src-size = 0)
// ---------------------------------------------------------------------------
__device__ __forceinline__ void cp_async4(uint32_t dst_smem, const float* src, bool valid)
{
    int sz = valid ? 4 : 0;
    asm volatile("cp.async.ca.shared.global [%0], [%1], 4, %2;"
                 :: "r"(dst_smem), "l"(src), "r"(sz));
}
__device__ __forceinline__ void cp_commit() { asm volatile("cp.async.commit_group;"); }
__device__ __forceinline__ void cp_wait0()  { asm volatile("cp.async.wait_group 0;"); }
__device__ __forceinline__ uint32_t smem_u32(const void* p)
{
    return (uint32_t)__cvta_generic_to_shared(p);
}

// ---------------------------------------------------------------------------
// Device scratch
// ---------------------------------------------------------------------------
__device__ float g_fea2down[B * 128 * H2 * W2];
__device__ float g_fea1    [B * C   * H1 * W1];
__device__ float g_fea2    [B * C   * H2 * W2];
__device__ float g_up1     [B * C   * H1 * W1];
__device__ float g_fea     [B * C   * H1 * W1];
__device__ float g_off1    [B * 18  * H1 * W1];
__device__ float g_fea11   [B * C   * H1 * W1];
__device__ float g_rs2     [B * C   * H2 * W2];
__device__ float g_off2    [B * 18  * H2 * W2];
__device__ float g_fea2d   [B * C   * H2 * W2];
__device__ float g_up2     [B * C   * H1 * W1];
__device__ float g_wq1     [4 * C * 4 * C];
__device__ float g_wq2     [4 * C * 4 * C];

// ---------------------------------------------------------------------------
// conv3x3 v6 (STRIDE 1): block = 32 cols x 8 rows x 32 out-ch. 128 threads:
// colg=tid&3 (8-col group), row=(tid>>2)&7, cog=tid>>5 (8-ch group).
// Each thread: 8 adjacent pixels x 8 channels as 4 f32x2 pixel-pairs/channel.
// Weight reads are warp-broadcast scalars. cp.async double-buffered staging.
// ---------------------------------------------------------------------------
template <int CI_BLK>
__global__ __launch_bounds__(128, 4)
void conv3x3_v6(const float* __restrict__ inA, const float* __restrict__ inB,
                int C0, int Cin,
                const float* __restrict__ w, const float* __restrict__ bias,
                float* __restrict__ out, int Cout,
                int H, int W, int Ho, int Wo)
{
    constexpr int XR = 10;
    constexpr int XC = 34;
    constexpr int XP = 35;
    constexpr int NX = 10;
    __shared__ __align__(16) float xs[2][CI_BLK][XR * XP];
    __shared__ __align__(16) float w_s[2][CI_BLK][9][32];

    const int tid  = threadIdx.x;
    const int colg = tid & 3;
    const int row  = (tid >> 2) & 7;
    const int cog  = tid >> 5;
    const int col0 = colg * 8;
    const int nchunk = Cout >> 5;
    const int b     = blockIdx.z / nchunk;
    const int chunk = blockIdx.z % nchunk;
    const int co_base = chunk * 32;
    const int ow0 = blockIdx.x * 32;
    const int oh0 = blockIdx.y * 8;
    const int HW = H * W;

    unsigned long long acc[8][4];
#pragma unroll
    for (int co = 0; co < 8; co++)
#pragma unroll
        for (int j = 0; j < 4; j++) acc[co][j] = 0ull;

    auto stage = [&](int sb, int cb) {
        for (int i = tid; i < CI_BLK * XR * XC; i += 128) {
            int ci  = i / (XR * XC);
            int rem = i % (XR * XC);
            int lr = rem / XC, lc = rem % XC;
            int r = oh0 - 1 + lr;
            int c = ow0 - 1 + lc;
            int cig = cb + ci;
            const float* src = (cig < C0)
                ? (inA + ((size_t)b * C0 + cig) * HW)
                : (inB + ((size_t)b * (Cin - C0) + (cig - C0)) * HW);
            bool valid = (r >= 0 && r < H && c >= 0 && c < W);
            cp_async4(smem_u32(&xs[sb][ci][lr * XP + lc]),
                      src + (valid ? r * W + c : 0), valid);
        }
        for (int i = tid; i < CI_BLK * 9 * 32; i += 128) {
            int o = i & 31, tap = (i >> 5) % 9, ci = i / 288;
            cp_async4(smem_u32(&w_s[sb][ci][tap][o]),
                      w + ((size_t)(co_base + o) * Cin + cb + ci) * 9 + tap, true);
        }
        cp_commit();
    };

    stage(0, 0);
    const int nst = Cin / CI_BLK;
    for (int s = 0; s < nst; s++) {
        cp_wait0();
        __syncthreads();
        if (s + 1 < nst) stage((s + 1) & 1, (s + 1) * CI_BLK);
        const int sb = s & 1;

        for (int ci = 0; ci < CI_BLK; ci++) {
            const float* xc = xs[sb][ci];
#pragma unroll
            for (int kh = 0; kh < 3; kh++) {
                float x[NX];
                {
                    const float* xr = xc + (row + kh) * XP + col0;
#pragma unroll
                    for (int i = 0; i < NX; i++) x[i] = xr[i];
                }
#pragma unroll
                for (int kw = 0; kw < 3; kw++) {
                    unsigned long long ap[4];
#pragma unroll
                    for (int j = 0; j < 4; j++)
                        ap[j] = pack_pair(x[2 * j + kw], x[2 * j + 1 + kw]);
                    const float* wp = w_s[sb][ci][kh * 3 + kw] + cog * 8;
#pragma unroll
                    for (int co = 0; co < 8; co++) {
                        unsigned long long ww = pack2(wp[co]);
                        fma2(acc[co][0], ap[0], ww);
                        fma2(acc[co][1], ap[1], ww);
                        fma2(acc[co][2], ap[2], ww);
                        fma2(acc[co][3], ap[3], ww);
                    }
                }
            }
        }
    }

    const int oh = oh0 + row;
#pragma unroll
    for (int co = 0; co < 8; co++) {
        int og = co_base + cog * 8 + co;
        float bv = bias[og];
        float* op = out + (((size_t)b * Cout + og) * Ho + oh) * Wo + ow0 + col0;
#pragma unroll
        for (int j = 0; j < 4; j++) {
            float2 v = unpack2(acc[co][j]);
            op[2 * j]     = v.x + bv;
            op[2 * j + 1] = v.y + bv;
        }
    }
}

// ---------------------------------------------------------------------------
// conv3x3 v5 (STRIDE 2, R11 proven): 16x16 tile, 2 px/thread, 32 out-ch
// chunk, cp.async double-buffered.
// ---------------------------------------------------------------------------
template <int STRIDE, int CI_BLK>
__global__ __launch_bounds__(128, 4)
void conv3x3_v5(const float* __restrict__ inA, const float* __restrict__ inB,
                int C0, int Cin,
                const float* __restrict__ w, const float* __restrict__ bias,
                float* __restrict__ out, int Cout,
                int H, int W, int Ho, int Wo)
{
    constexpr int XR = 15 * STRIDE + 3;
    constexpr int XC = 15 * STRIDE + 3;
    constexpr int XP = XC + (STRIDE == 1 ? 1 : 2);
    __shared__ __align__(16) float xs[2][CI_BLK][XR * XP];
    __shared__ __align__(16) float w_s[2][CI_BLK][9][32];

    const int tid = threadIdx.x;
    const int tx = tid & 15, ty = tid >> 4;
    const int nchunk = Cout >> 5;
    const int b     = blockIdx.z / nchunk;
    const int chunk = blockIdx.z % nchunk;
    const int co_base = chunk * 32;
    const int ow0 = blockIdx.x * 16;
    const int oh0 = blockIdx.y * 16;
    const int HW = H * W;

    unsigned long long acc[2][16];
#pragma unroll
    for (int a = 0; a < 2; a++)
#pragma unroll
        for (int o = 0; o < 16; o++) acc[a][o] = 0ull;

    auto stage = [&](int sb, int cb) {
        for (int i = tid; i < CI_BLK * XR * XC; i += 128) {
            int ci  = i / (XR * XC);
            int rem = i % (XR * XC);
            int lr = rem / XC, lc = rem % XC;
            int r = oh0 * STRIDE - 1 + lr;
            int c = ow0 * STRIDE - 1 + lc;
            int cig = cb + ci;
            const float* src = (cig < C0)
                ? (inA + ((size_t)b * C0 + cig) * HW)
                : (inB + ((size_t)b * (Cin - C0) + (cig - C0)) * HW);
            bool valid = (r >= 0 && r < H && c >= 0 && c < W);
            cp_async4(smem_u32(&xs[sb][ci][lr * XP + lc]),
                      src + (valid ? r * W + c : 0), valid);
        }
        for (int i = tid; i < CI_BLK * 9 * 32; i += 128) {
            int o = i & 31, tap = (i >> 5) % 9, ci = i / 288;
            cp_async4(smem_u32(&w_s[sb][ci][tap][o]),
                      w + ((size_t)(co_base + o) * Cin + cb + ci) * 9 + tap, true);
        }
        cp_commit();
    };

    stage(0, 0);
    const int nst = Cin / CI_BLK;
    for (int s = 0; s < nst; s++) {
        cp_wait0();
        __syncthreads();
        if (s + 1 < nst) stage((s + 1) & 1, (s + 1) * CI_BLK);
        const int sb = s & 1;

        for (int ci = 0; ci < CI_BLK; ci++) {
            const float* xc = xs[sb][ci];
#pragma unroll
            for (int kh = 0; kh < 3; kh++) {
                float xv[2][3];
#pragma unroll
                for (int a = 0; a < 2; a++) {
                    int rrow = (ty + 8 * a) * STRIDE + kh;
                    int ccol = tx * STRIDE;
#pragma unroll
                    for (int kw = 0; kw < 3; kw++)
                        xv[a][kw] = xc[rrow * XP + ccol + kw];
                }
#pragma unroll
                for (int kw = 0; kw < 3; kw++) {
                    unsigned long long xx0 = pack2(xv[0][kw]);
                    unsigned long long xx1 = pack2(xv[1][kw]);
                    const ulonglong2* w2 = (const ulonglong2*)w_s[sb][ci][kh * 3 + kw];
#pragma unroll
                    for (int o8 = 0; o8 < 8; o8++) {
                        ulonglong2 wv = w2[o8];
                        fma2(acc[0][o8 * 2 + 0], xx0, wv.x);
                        fma2(acc[0][o8 * 2 + 1], xx0, wv.y);
                        fma2(acc[1][o8 * 2 + 0], xx1, wv.x);
                        fma2(acc[1][o8 * 2 + 1], xx1, wv.y);
                    }
                }
            }
        }
    }

#pragma unroll
    for (int a = 0; a < 2; a++) {
        int oh = oh0 + ty + 8 * a;
        int ow = ow0 + tx;
#pragma unroll
        for (int o2 = 0; o2 < 16; o2++) {
            float2 v = unpack2(acc[a][o2]);
            int og = co_base + 2 * o2;
            out[(((size_t)b * Cout + og) * Ho + oh) * Wo + ow]     = v.x + bias[og];
            out[(((size_t)b * Cout + og + 1) * Ho + oh) * Wo + ow] = v.y + bias[og + 1];
        }
    }
}

// ---------------------------------------------------------------------------
// Old-style 3x3 conv for the offset heads (Cout=18, CO=20 register block).
// ---------------------------------------------------------------------------
template <int STRIDE, int CO>
__global__ __launch_bounds__(256)
void conv3x3_kernel(const float* __restrict__ inA, const float* __restrict__ inB,
                    int C0, int Cin,
                    const float* __restrict__ w, const float* __restrict__ bias,
                    float* __restrict__ out, int Cout,
                    int H, int W, int Ho, int Wo)
{
    constexpr int XR = 7 * STRIDE + 3;
    constexpr int XC = 31 * STRIDE + 3;
    constexpr int XP = XC + (STRIDE == 2 ? 1 : 0);
    __shared__ __align__(16) float xs[XR * XP];
    __shared__ __align__(16) float w_s[9 * CO];

    const int tid = threadIdx.x;
    const int tx = tid & 31, ty = tid >> 5;
    const int nchunk = (Cout + CO - 1) / CO;
    const int b     = blockIdx.z / nchunk;
    const int chunk = blockIdx.z % nchunk;
    const int co_base = chunk * CO;
    const int ow0 = blockIdx.x * 32;
    const int oh0 = blockIdx.y * 8;
    const int HW = H * W;

    unsigned long long acc[CO / 2];
#pragma unroll
    for (int o = 0; o < CO / 2; o++) acc[o] = 0ull;

    for (int ci = 0; ci < Cin; ci++) {
        const float* src = (ci < C0)
            ? (inA + ((size_t)b * C0 + ci) * HW)
            : (inB + ((size_t)b * (Cin - C0) + (ci - C0)) * HW);
        __syncthreads();
        for (int i = tid; i < XR * XC; i += 256) {
            int lr = i / XC, lc = i % XC;
            int r = oh0 * STRIDE - 1 + lr;
            int c = ow0 * STRIDE - 1 + lc;
            xs[lr * XP + lc] = (r >= 0 && r < H && c >= 0 && c < W) ? src[r * W + c] : 0.f;
        }
        for (int i = tid; i < 9 * CO; i += 256) {
            int tap = i / CO, o = i % CO;
            int og = co_base + o;
            w_s[tap * CO + o] = (og < Cout) ? w[((size_t)og * Cin + ci) * 9 + tap] : 0.f;
        }
        __syncthreads();

        float xv[9];
#pragma unroll
        for (int kh = 0; kh < 3; kh++)
#pragma unroll
            for (int kw = 0; kw < 3; kw++)
                xv[kh * 3 + kw] = xs[(ty * STRIDE + kh) * XP + tx * STRIDE + kw];

#pragma unroll
        for (int tap = 0; tap < 9; tap++) {
            unsigned long long xx = pack2(xv[tap]);
            const ulonglong2* w2 = (const ulonglong2*)(w_s + tap * CO);
#pragma unroll
            for (int o4 = 0; o4 < CO / 4; o4++) {
                ulonglong2 wv = w2[o4];
                fma2(acc[o4 * 2 + 0], xx, wv.x);
                fma2(acc[o4 * 2 + 1], xx, wv.y);
            }
        }
    }

    const int oh = oh0 + ty, ow = ow0 + tx;
    if (oh < Ho && ow < Wo) {
#pragma unroll
        for (int o2 = 0; o2 < CO / 2; o2++) {
            float2 v = unpack2(acc[o2]);
            int og0 = co_base + 2 * o2;
            if (og0 < Cout)
                out[(((size_t)b * Cout + og0) * Ho + oh) * Wo + ow] = v.x + bias[og0];
            if (og0 + 1 < Cout)
                out[(((size_t)b * Cout + og0 + 1) * Ho + oh) * Wo + ow] = v.y + bias[og0 + 1];
        }
    }
}

// ---------------------------------------------------------------------------
// Weight repack for transposed conv (4x4, stride 2, pad 1).
// ---------------------------------------------------------------------------
__global__ void prep_wq_kernel(const float* __restrict__ w, float* __restrict__ wq)
{
    int idx = blockIdx.x * 256 + threadIdx.x;
    if (idx >= 4 * C * 4 * C) return;
    int o  = idx & 63;
    int t  = (idx >> 6) & 3;
    int ci = (idx >> 8) & 63;
    int pc = idx >> 14;
    int pa = pc >> 1, pb = pc & 1;
    int di = t >> 1, dj = t & 1;
    int kh = 3 - pa - 2 * di;
    int kw = 3 - pb - 2 * dj;
    wq[idx] = w[((ci * C + o) * 4 + kh) * 4 + kw];
}

// ---------------------------------------------------------------------------
// convt v3: convt_v2 + cp.async DOUBLE-BUFFERED staging.
// 128 threads, 2 px/thread, 32 out-ch per z-slice, 8-ch ci chunks.
// blockIdx.z = ((b*4 + pc)*2 + coh)
// ---------------------------------------------------------------------------
template <int CI_BLK>
__global__ __launch_bounds__(128)
void convt_v3(const float* __restrict__ in, const float* __restrict__ wq,
              const float* __restrict__ bias, float* __restrict__ out,
              int Hin, int Win)
{
    __shared__ __align__(16) float xs[2][CI_BLK][9 * 35];
    __shared__ __align__(16) float w_s[2][CI_BLK][4][32];

    const int tid = threadIdx.x;
    const int tx = tid & 15, ty = tid >> 4;
    const int zc = blockIdx.z;
    const int b   = zc >> 3;
    const int pc  = (zc >> 1) & 3;
    const int coh = zc & 1;
    const int co_base = coh * 32;
    const int pa = pc >> 1, pb = pc & 1;
    const int j0 = blockIdx.x * 32;
    const int i0 = blockIdx.y * 8;
    const int HWin = Hin * Win;
    const float* inb = in + (size_t)b * C * HWin;

    unsigned long long acc[2][16];
#pragma unroll
    for (int bb = 0; bb < 2; bb++)
#pragma unroll
        for (int o = 0; o < 16; o++) acc[bb][o] = 0ull;

    auto stage = [&](int sb, int cb) {
        for (int i = tid; i < CI_BLK * 9 * 34; i += 128) {
            int ci = i / (9 * 34);
            int rem = i % (9 * 34);
            int lr = rem / 34, lc = rem % 34;
            int r = i0 + pa - 1 + lr;
            int c = j0 + pb - 1 + lc;
            bool valid = (r >= 0 && r < Hin && c >= 0 && c < Win);
            cp_async4(smem_u32(&xs[sb][ci][lr * 35 + lc]),
                      inb + (size_t)(cb + ci) * HWin + (valid ? r * Win + c : 0), valid);
        }
        for (int i = tid; i < CI_BLK * 4 * 32; i += 128) {
            int o = i & 31, t = (i >> 5) & 3, ci = i >> 7;
            cp_async4(smem_u32(&w_s[sb][ci][t][o]),
                      wq + (size_t)pc * (C * 4 * C) + (cb + ci) * (4 * C) + t * C + co_base + o,
                      true);
        }
        cp_commit();
    };

    stage(0, 0);
    const int nst = C / CI_BLK;
    for (int s = 0; s < nst; s++) {
        cp_wait0();
        __syncthreads();
        if (s + 1 < nst) stage((s + 1) & 1, (s + 1) * CI_BLK);
        const int sb = s & 1;

        for (int ci = 0; ci < CI_BLK; ci++) {
            const float* xc = xs[sb][ci];
            float xv[2][2][2];
#pragma unroll
            for (int di = 0; di < 2; di++)
#pragma unroll
                for (int bb = 0; bb < 2; bb++)
#pragma unroll
                    for (int dj = 0; dj < 2; dj++)
                        xv[di][bb][dj] = xc[(ty + di) * 35 + tx + 16 * bb + dj];

#pragma unroll
            for (int t = 0; t < 4; t++) {
                int di = t >> 1, dj = t & 1;
                unsigned long long xx[2];
                xx[0] = pack2(xv[di][0][dj]);
                xx[1] = pack2(xv[di][1][dj]);
                const ulonglong2* w2 = (const ulonglong2*)w_s[sb][ci][t];
#pragma unroll
                for (int o8 = 0; o8 < 8; o8++) {
                    ulonglong2 wv = w2[o8];
#pragma unroll
                    for (int bb = 0; bb < 2; bb++) {
                        fma2(acc[bb][o8 * 2 + 0], xx[bb], wv.x);
                        fma2(acc[bb][o8 * 2 + 1], xx[bb], wv.y);
                    }
                }
            }
        }
    }

    const int Hout = 2 * Hin, Wout = 2 * Win;
    const int oh = 2 * (i0 + ty) + pa;
#pragma unroll
    for (int bb = 0; bb < 2; bb++) {
        int ow = 2 * (j0 + tx + 16 * bb) + pb;
#pragma unroll
        for (int o2 = 0; o2 < 16; o2++) {
            float2 v = unpack2(acc[bb][o2]);
            int og = co_base + 2 * o2;
            out[(((size_t)b * C + og) * Hout + oh) * Wout + ow]     = v.x + bias[og];
            out[(((size_t)b * C + og + 1) * Hout + oh) * Wout + ow] = v.y + bias[og + 1];
        }
    }
}

// ---------------------------------------------------------------------------
// 1x1 conv over (a + b2), C->C (256 threads, 1 px, 64 acc regs).
// ci loop unrolled x4 for LDG MLP.
// ---------------------------------------------------------------------------
__global__ __launch_bounds__(256)
void conv1x1_add_kernel(const float* __restrict__ a, const float* __restrict__ b2,
                        const float* __restrict__ w, const float* __restrict__ bias,
                        float* __restrict__ out, int HW)
{
    __shared__ __align__(16) float w_s[C * C];   // [ci][o]
    const int tid = threadIdx.x;
    for (int i = tid; i < C * C; i += 256) {
        int ci = i >> 6, o = i & 63;
        w_s[i] = w[o * C + ci];
    }
    __syncthreads();

    const int pix = blockIdx.x * 256 + tid;
    const int b = blockIdx.y;
    if (pix >= HW) return;
    const float* ab = a  + (size_t)b * C * HW + pix;
    const float* bb = b2 + (size_t)b * C * HW + pix;

    unsigned long long acc[C / 2];
#pragma unroll
    for (int o = 0; o < C / 2; o++) acc[o] = 0ull;

#pragma unroll 4
    for (int ci = 0; ci < C; ci++) {
        unsigned long long xx = pack2(ab[(size_t)ci * HW] + bb[(size_t)ci * HW]);
        const ulonglong2* w2 = (const ulonglong2*)(w_s + ci * C);
#pragma unroll
        for (int o4 = 0; o4 < C / 4; o4++) {
            ulonglong2 wv = w2[o4];
            fma2(acc[o4 * 2 + 0], xx, wv.x);
            fma2(acc[o4 * 2 + 1], xx, wv.y);
        }
    }
    float* ob = out + (size_t)b * C * HW + pix;
#pragma unroll
    for (int o2 = 0; o2 < C / 2; o2++) {
        float2 v = unpack2(acc[o2]);
        ob[(size_t)(2 * o2) * HW]     = v.x + bias[2 * o2];
        ob[(size_t)(2 * o2 + 1) * HW] = v.y + bias[2 * o2 + 1];
    }
}

// ---------------------------------------------------------------------------
// Deformable conv (256 threads, 1 px, 64 acc regs) with cp.async
// double-buffered per-tap weight staging. c loop unrolled x2 for gather MLP.
// Reference-exact.
// ---------------------------------------------------------------------------
__global__ __launch_bounds__(256)
void deform_db(const float* __restrict__ x, const float* __restrict__ off,
               const float* __restrict__ w, const float* __restrict__ bias,
               float* __restrict__ out, int H, int W)
{
    __shared__ __align__(16) float w_s[2][C * C];   // [c][o], double-buffered
    const int tid = threadIdx.x;
    const int tx = tid & 31, ty = tid >> 5;
    const int ow = blockIdx.x * 32 + tx;
    const int oh = blockIdx.y * 8 + ty;
    const int b  = blockIdx.z;
    const int HW = H * W;
    const float* xb   = x   + (size_t)b * C * HW;
    const float* offb = off + (size_t)b * 18 * HW;
    const int pix = oh * W + ow;

    unsigned long long acc[C / 2];
#pragma unroll
    for (int o = 0; o < C / 2; o++) acc[o] = 0ull;

    const float rmax = (float)(H + 1);
    const float cmax = (float)(W + 1);

    auto stage = [&](int sb, int n) {
        for (int i = tid; i < C * C; i += 256) {
            int c = i >> 6, o = i & 63;
            cp_async4(smem_u32(&w_s[sb][i]), w + (size_t)o * (C * 9) + c * 9 + n, true);
        }
        cp_commit();
    };

    stage(0, 0);
    for (int n = 0; n < 9; n++) {
        cp_wait0();
        __syncthreads();
        if (n + 1 < 9) stage((n + 1) & 1, n + 1);
        const float* ws = w_s[n & 1];

        float offr = offb[(size_t)n * HW + pix];
        float offc = offb[(size_t)(9 + n) * HW + pix];
        float pr  = (float)(oh + (n / 3)) + offr;
        float pcc = (float)(ow + (n % 3)) + offc;
        pr  = fminf(fmaxf(pr, 0.f), rmax);
        pcc = fminf(fmaxf(pcc, 0.f), cmax);
        float r0f = floorf(pr), c0f = floorf(pcc);
        int r0 = (int)r0f, c0 = (int)c0f;
        int r1 = min(r0 + 1, H + 1), c1 = min(c0 + 1, W + 1);
        float fr = pr - r0f, fc = pcc - c0f;
        float w00 = (1.f - fr) * (1.f - fc);
        float w01 = (1.f - fr) * fc;
        float w10 = fr * (1.f - fc);
        float w11 = fr * fc;

        int rr0 = r0 - 1, rr1 = r1 - 1, cc0 = c0 - 1, cc1 = c1 - 1;
        bool vr0 = (rr0 >= 0) && (rr0 < H);
        bool vr1 = (rr1 >= 0) && (rr1 < H);
        bool vc0 = (cc0 >= 0) && (cc0 < W);
        bool vc1 = (cc1 >= 0) && (cc1 < W);
        float m00 = (vr0 && vc0) ? w00 : 0.f;
        float m01 = (vr0 && vc1) ? w01 : 0.f;
        float m10 = (vr1 && vc0) ? w10 : 0.f;
        float m11 = (vr1 && vc1) ? w11 : 0.f;
        int sr0 = vr0 ? rr0 : 0, sr1 = vr1 ? rr1 : 0;
        int sc0 = vc0 ? cc0 : 0, sc1 = vc1 ? cc1 : 0;
        int i00 = sr0 * W + sc0;
        int i01 = sr0 * W + sc1;
        int i10 = sr1 * W + sc0;
        int i11 = sr1 * W + sc1;

#pragma unroll 2
        for (int c = 0; c < C; c++) {
            const float* xc = xb + (size_t)c * HW;
            float v = m00 * xc[i00] + m01 * xc[i01] + m10 * xc[i10] + m11 * xc[i11];
            unsigned long long vv = pack2(v);
            const ulonglong2* w2 = (const ulonglong2*)(ws + c * C);
#pragma unroll
            for (int o4 = 0; o4 < C / 4; o4++) {
                ulonglong2 wv = w2[o4];
                fma2(acc[o4 * 2 + 0], vv, wv.x);
                fma2(acc[o4 * 2 + 1], vv, wv.y);
            }
        }
    }

    if (oh < H && ow < W) {
#pragma unroll
        for (int o2 = 0; o2 < C / 2; o2++) {
            float2 v = unpack2(acc[o2]);
            out[(((size_t)b * C + 2 * o2) * H + oh) * W + ow]     = v.x + bias[2 * o2];
            out[(((size_t)b * C + 2 * o2 + 1) * H + oh) * W + ow] = v.y + bias[2 * o2 + 1];
        }
    }
}

// ---------------------------------------------------------------------------
// Launch
// ---------------------------------------------------------------------------
static float* sym(const void* s)
{
    void* p = nullptr;
    cudaGetSymbolAddress(&p, s);
    return (float*)p;
}

extern "C" void kernel_launch(void* const* d_in, const int* in_sizes, int n_in,
                              void* d_out, int out_size)
{
    const float* dem      = (const float*)d_in[0];
    const float* rs       = (const float*)d_in[1];
    const float* w_down1  = (const float*)d_in[2];
    const float* b_down1  = (const float*)d_in[3];
    const float* w_c1     = (const float*)d_in[4];
    const float* b_c1     = (const float*)d_in[5];
    const float* w_c12    = (const float*)d_in[6];
    const float* b_c12    = (const float*)d_in[7];
    const float* w_up1    = (const float*)d_in[8];
    const float* b_up1    = (const float*)d_in[9];
    const float* w_downrs = (const float*)d_in[10];
    const float* b_downrs = (const float*)d_in[11];
    const float* w_off    = (const float*)d_in[12];
    const float* b_off    = (const float*)d_in[13];
    const float* w_c3     = (const float*)d_in[14];
    const float* b_c3     = (const float*)d_in[15];
    const float* w_d1o    = (const float*)d_in[16];
    const float* b_d1o    = (const float*)d_in[17];
    const float* w_d1     = (const float*)d_in[18];
    const float* b_d1     = (const float*)d_in[19];
    const float* w_d2o    = (const float*)d_in[20];
    const float* b_d2o    = (const float*)d_in[21];
    const float* w_d2     = (const float*)d_in[22];
    const float* b_d2     = (const float*)d_in[23];
    const float* w_up2    = (const float*)d_in[24];
    const float* b_up2    = (const float*)d_in[25];
    float* outp = (float*)d_out;

    static float* fea2down = sym(g_fea2down);
    static float* fea1     = sym(g_fea1);
    static float* fea2     = sym(g_fea2);
    static float* up1      = sym(g_up1);
    static float* fea      = sym(g_fea);
    static float* off1     = sym(g_off1);
    static float* fea11    = sym(g_fea11);
    static float* rs2      = sym(g_rs2);
    static float* off2     = sym(g_off2);
    static float* fea2d    = sym(g_fea2d);
    static float* up2      = sym(g_up2);
    static float* wq1      = sym(g_wq1);
    static float* wq2      = sym(g_wq2);

    // Weight repacks first
    prep_wq_kernel<<<dim3((4 * C * 4 * C + 255) / 256), 256>>>(w_up1, wq1);
    prep_wq_kernel<<<dim3((4 * C * 4 * C + 255) / 256), 256>>>(w_up2, wq2);

    // 1) fea_2 = conv(cat, w_down1, s=2) : (B,128,128,128)   v5, nchunk=4
    conv3x3_v5<2, 4><<<dim3(W2 / 16, H2 / 16, B * 4), 128>>>(
        dem, rs, C, 2 * C, w_down1, b_down1, fea2down, 2 * C, H1, W1, H2, W2);

    // 2) fea_1 = conv(cat, w_c1, s=1) : (B,64,256,256)       v6, nchunk=2
    conv3x3_v6<8><<<dim3(W1 / 32, H1 / 8, B * 2), 128>>>(
        dem, rs, C, 2 * C, w_c1, b_c1, fea1, C, H1, W1, H1, W1);

    // 3) fea_2 = conv(fea_2, w_c12, s=1) : (B,64,128,128)    v6, nchunk=2
    conv3x3_v6<8><<<dim3(W2 / 32, H2 / 8, B * 2), 128>>>(
        fea2down, fea2down, 2 * C, 2 * C, w_c12, b_c12, fea2, C, H2, W2, H2, W2);

    // 4) fea_2_1 = convT(fea_2, w_up1) : (B,64,256,256)
    convt_v3<8><<<dim3(W2 / 32, H2 / 8, B * 8), 128>>>(fea2, wq1, b_up1, up1, H2, W2);

    // 5) fea = 1x1 conv(fea_1 + fea_2_1, w_off)
    conv1x1_add_kernel<<<dim3((H1 * W1) / 256, B), 256>>>(fea1, up1, w_off, b_off, fea, H1 * W1);

    // 6) offsets level 1 = conv(fea, w_d1o) : (B,18,256,256)
    conv3x3_kernel<1, 20><<<dim3(W1 / 32, H1 / 8, B), 256>>>(
        fea, fea, C, C, w_d1o, b_d1o, off1, 18, H1, W1, H1, W1);

    // 7) fea_1_1 = deform(rs, off1, w_d1)
    deform_db<<<dim3(W1 / 32, H1 / 8, B), 256>>>(rs, off1, w_d1, b_d1, fea11, H1, W1);

    // 8) rs_2 = conv(rs, w_downrs, s=2) : (B,64,128,128)     v5, nchunk=2
    conv3x3_v5<2, 4><<<dim3(W2 / 16, H2 / 16, B * 2), 128>>>(
        rs, rs, C, C, w_downrs, b_downrs, rs2, C, H1, W1, H2, W2);

    // 9) offsets level 2 = conv(fea_2, w_d2o) : (B,18,128,128)
    conv3x3_kernel<1, 20><<<dim3(W2 / 32, H2 / 8, B), 256>>>(
        fea2, fea2, C, C, w_d2o, b_d2o, off2, 18, H2, W2, H2, W2);

    // 10) fea_2 = deform(rs_2, off2, w_d2)
    deform_db<<<dim3(W2 / 32, H2 / 8, B), 256>>>(rs2, off2, w_d2, b_d2, fea2d, H2, W2);

    // 11) fea_2_1 = convT(fea_2, w_up2) : (B,64,256,256)
    convt_v3<8><<<dim3(W2 / 32, H2 / 8, B * 8), 128>>>(fea2d, wq2, b_up2, up2, H2, W2);

    // 12) out = 1x1 conv(fea_1_1 + fea_2_1, w_c3)
    conv1x1_add_kernel<<<dim3((H1 * W1) / 256, B), 256>>>(fea11, up2, w_c3, b_c3, outp, H1 * W1);
}